// round 1
// baseline (speedup 1.0000x reference)
#include <cuda_runtime.h>
#include <cuda_bf16.h>
#include <math.h>

#define N_NODES  50000
#define N_EDGES  1000000
#define N_QUERY  100000
#define FDIM     256     // NUM_FEATURES == HIDDEN == 256
#define KDIM     256

// ---------------- scratch (device globals: allocation-free) ----------------
__device__ float g_h1[(size_t)N_NODES * FDIM];   // x @ W1
__device__ float g_a1[(size_t)N_NODES * FDIM];   // scatter(h1) + b1   (relu applied on read)
__device__ float g_h2[(size_t)N_NODES * FDIM];   // relu(a1) @ W2
__device__ float g_a2[(size_t)N_NODES * FDIM];   // scatter(h2) + b2

// ---------------- helpers ----------------
__device__ __forceinline__ void red_add_v4(float4* addr, float4 v) {
    asm volatile("red.global.add.v4.f32 [%0], {%1,%2,%3,%4};"
                 :: "l"(addr), "f"(v.x), "f"(v.y), "f"(v.z), "f"(v.w)
                 : "memory");
}

// ---------------- GEMM: C[M,256] = act(A)[M,256] @ B[256,256] ----------------
template <bool RELU>
__global__ __launch_bounds__(256)
void sgemm_k256(const float* __restrict__ A, const float* __restrict__ B,
                float* __restrict__ C, int M)
{
    const int BM = 128, BN = 128, BK = 8;
    __shared__ float As[BK][BM + 4];
    __shared__ float Bs[BK][BN];

    int tid  = threadIdx.x;
    int row0 = blockIdx.x * BM;
    int col0 = blockIdx.y * BN;

    int tx = tid & 15;        // 0..15 -> 8 output cols each
    int ty = tid >> 4;        // 0..15 -> 8 output rows each

    int arow = tid >> 1;            // 0..127
    int acol = (tid & 1) * 4;       // 0 or 4
    int brow = tid >> 5;            // 0..7
    int bcol = (tid & 31) * 4;      // 0..124

    bool aval = (row0 + arow) < M;
    const float* Aptr = A + (size_t)(row0 + arow) * KDIM + acol;

    float acc[8][8];
#pragma unroll
    for (int i = 0; i < 8; i++)
#pragma unroll
        for (int j = 0; j < 8; j++) acc[i][j] = 0.f;

    for (int k0 = 0; k0 < KDIM; k0 += BK) {
        float4 av = aval ? *(const float4*)(Aptr + k0) : make_float4(0.f, 0.f, 0.f, 0.f);
        if (RELU) {
            av.x = fmaxf(av.x, 0.f); av.y = fmaxf(av.y, 0.f);
            av.z = fmaxf(av.z, 0.f); av.w = fmaxf(av.w, 0.f);
        }
        As[acol + 0][arow] = av.x;
        As[acol + 1][arow] = av.y;
        As[acol + 2][arow] = av.z;
        As[acol + 3][arow] = av.w;

        float4 bv = *(const float4*)(B + (size_t)(k0 + brow) * KDIM + col0 + bcol);
        *(float4*)&Bs[brow][bcol] = bv;

        __syncthreads();
#pragma unroll
        for (int k = 0; k < BK; k++) {
            float ra[8], rb[8];
#pragma unroll
            for (int i = 0; i < 8; i++) ra[i] = As[k][ty * 8 + i];
#pragma unroll
            for (int j = 0; j < 8; j++) rb[j] = Bs[k][tx * 8 + j];
#pragma unroll
            for (int i = 0; i < 8; i++)
#pragma unroll
                for (int j = 0; j < 8; j++) acc[i][j] += ra[i] * rb[j];
        }
        __syncthreads();
    }

#pragma unroll
    for (int i = 0; i < 8; i++) {
        int r = row0 + ty * 8 + i;
        if (r < M) {
            float4* cp = (float4*)(C + (size_t)r * KDIM + col0 + tx * 8);
            float4 v0 = make_float4(acc[i][0], acc[i][1], acc[i][2], acc[i][3]);
            float4 v1 = make_float4(acc[i][4], acc[i][5], acc[i][6], acc[i][7]);
            cp[0] = v0;
            cp[1] = v1;
        }
    }
}

// ---------------- init: agg[n][f] = b[f] ----------------
__global__ void init_bias_kernel(float* __restrict__ agg, const float* __restrict__ b)
{
    int i = blockIdx.x * blockDim.x + threadIdx.x;      // float4 index
    const int total = N_NODES * (FDIM / 4);
    if (i < total) {
        ((float4*)agg)[i] = ((const float4*)b)[i & 63];
    }
}

// ---------------- scatter: agg[dst] += w_e * h[src] (one warp / edge) ----------------
__global__ __launch_bounds__(256)
void scatter_kernel(const float* __restrict__ h,
                    const int* __restrict__ edge_index,   // [2, E]
                    const float* __restrict__ w,
                    float* __restrict__ agg)
{
    int warp = (blockIdx.x * blockDim.x + threadIdx.x) >> 5;
    int lane = threadIdx.x & 31;
    if (warp >= N_EDGES) return;

    int   s  = edge_index[warp];
    int   d  = edge_index[N_EDGES + warp];
    float we = w[warp];

    const float4* hs = (const float4*)(h + (size_t)s * FDIM);
    float4*       ad = (float4*)(agg + (size_t)d * FDIM);

#pragma unroll
    for (int c = 0; c < 2; c++) {
        int f4 = lane + 32 * c;       // 0..63
        float4 v = hs[f4];
        v.x *= we; v.y *= we; v.z *= we; v.w *= we;
        red_add_v4(&ad[f4], v);
    }
}

// ---------------- query head: concat-GEMV + log_softmax (one warp / query) ----------------
__global__ __launch_bounds__(256)
void final_kernel(const float* __restrict__ h,
                  const int* __restrict__ q,          // [Q, 2]
                  const float* __restrict__ Wl,       // [512, 2]
                  const float* __restrict__ bl,       // [2]
                  float* __restrict__ out)            // [Q, 2]
{
    __shared__ float sW[512 * 2];
    __shared__ float sb[2];
    for (int i = threadIdx.x; i < 1024; i += blockDim.x) sW[i] = Wl[i];
    if (threadIdx.x < 2) sb[threadIdx.x] = bl[threadIdx.x];
    __syncthreads();

    int warp = (blockIdx.x * blockDim.x + threadIdx.x) >> 5;
    int lane = threadIdx.x & 31;
    if (warp >= N_QUERY) return;

    int qa = q[2 * warp];
    int qb = q[2 * warp + 1];

    const float4* ha = (const float4*)(h + (size_t)qa * FDIM);
    const float4* hb = (const float4*)(h + (size_t)qb * FDIM);

    float acc0 = 0.f, acc1 = 0.f;
#pragma unroll
    for (int c = 0; c < 2; c++) {
        int f4 = lane + 32 * c;       // 0..63
        int f  = f4 * 4;              // feature 0..255
        float4 v = ha[f4];
        acc0 += v.x * sW[(f + 0) * 2 + 0] + v.y * sW[(f + 1) * 2 + 0]
              + v.z * sW[(f + 2) * 2 + 0] + v.w * sW[(f + 3) * 2 + 0];
        acc1 += v.x * sW[(f + 0) * 2 + 1] + v.y * sW[(f + 1) * 2 + 1]
              + v.z * sW[(f + 2) * 2 + 1] + v.w * sW[(f + 3) * 2 + 1];
        float4 u = hb[f4];
        int g = (256 + f);
        acc0 += u.x * sW[(g + 0) * 2 + 0] + u.y * sW[(g + 1) * 2 + 0]
              + u.z * sW[(g + 2) * 2 + 0] + u.w * sW[(g + 3) * 2 + 0];
        acc1 += u.x * sW[(g + 0) * 2 + 1] + u.y * sW[(g + 1) * 2 + 1]
              + u.z * sW[(g + 2) * 2 + 1] + u.w * sW[(g + 3) * 2 + 1];
    }
#pragma unroll
    for (int off = 16; off > 0; off >>= 1) {
        acc0 += __shfl_down_sync(0xFFFFFFFFu, acc0, off);
        acc1 += __shfl_down_sync(0xFFFFFFFFu, acc1, off);
    }
    if (lane == 0) {
        float l0 = acc0 + sb[0];
        float l1 = acc1 + sb[1];
        float m  = fmaxf(l0, l1);
        float lse = m + logf(expf(l0 - m) + expf(l1 - m));
        out[2 * warp]     = l0 - lse;
        out[2 * warp + 1] = l1 - lse;
    }
}

// ---------------- launch ----------------
extern "C" void kernel_launch(void* const* d_in, const int* in_sizes, int n_in,
                              void* d_out, int out_size)
{
    const float* x    = (const float*)d_in[0];
    const int*   ei   = (const int*)  d_in[1];
    const int*   qe   = (const int*)  d_in[2];
    const float* ew   = (const float*)d_in[3];
    const float* W1   = (const float*)d_in[4];
    const float* b1   = (const float*)d_in[5];
    const float* W2   = (const float*)d_in[6];
    const float* b2   = (const float*)d_in[7];
    const float* Wl   = (const float*)d_in[8];
    const float* bl   = (const float*)d_in[9];
    float*       out  = (float*)d_out;

    float *h1, *a1, *h2, *a2;
    cudaGetSymbolAddress((void**)&h1, g_h1);
    cudaGetSymbolAddress((void**)&a1, g_a1);
    cudaGetSymbolAddress((void**)&h2, g_h2);
    cudaGetSymbolAddress((void**)&a2, g_a2);

    dim3 gemm_grid((N_NODES + 127) / 128, 2);

    // conv1
    sgemm_k256<false><<<gemm_grid, 256>>>(x, W1, h1, N_NODES);
    {
        int total = N_NODES * (FDIM / 4);
        init_bias_kernel<<<(total + 255) / 256, 256>>>(a1, b1);
    }
    scatter_kernel<<<(N_EDGES * 32 + 255) / 256, 256>>>(h1, ei, ew, a1);

    // conv2 (relu fused into A-load)
    sgemm_k256<true><<<gemm_grid, 256>>>(a1, W2, h2, N_NODES);
    {
        int total = N_NODES * (FDIM / 4);
        init_bias_kernel<<<(total + 255) / 256, 256>>>(a2, b2);
    }
    scatter_kernel<<<(N_EDGES * 32 + 255) / 256, 256>>>(h2, ei, ew, a2);

    // link-prediction head
    final_kernel<<<(N_QUERY * 32 + 255) / 256, 256>>>(a2, qe, Wl, bl, out);
}

// round 2
// speedup vs baseline: 1.3488x; 1.3488x over previous
#include <cuda_runtime.h>
#include <cuda_bf16.h>
#include <math.h>

#define N_NODES  50000
#define N_EDGES  1000000
#define N_QUERY  100000
#define FDIM     256
#define KDIM     256
#define NB_SCAN  ((N_NODES + 255) / 256)   // 196

// ---------------- scratch (device globals: allocation-free) ----------------
__device__ float g_h[(size_t)N_NODES * FDIM];   // GEMM output (h1, then h2)
__device__ float g_a[(size_t)N_NODES * FDIM];   // aggregate output (a1relu, then a2)
__device__ int   g_counts[N_NODES];
__device__ int   g_cursor[N_NODES];
__device__ int   g_offsets[N_NODES + 1];
__device__ int   g_blocksums[NB_SCAN];
__device__ int2  g_edges[N_EDGES];              // {src, bits(w)} sorted by dst

// ---------------- CSR build ----------------
__global__ void zero_kernel(int* __restrict__ counts, int* __restrict__ cursor)
{
    int i = blockIdx.x * blockDim.x + threadIdx.x;
    if (i < N_NODES) { counts[i] = 0; cursor[i] = 0; }
}

__global__ void count_kernel(const int* __restrict__ edge_index, int* __restrict__ counts)
{
    int e = blockIdx.x * blockDim.x + threadIdx.x;
    if (e < N_EDGES) atomicAdd(&counts[edge_index[N_EDGES + e]], 1);
}

// per-block exclusive scan of counts -> offsets(partial), blocksums
__global__ void scan_part1(const int* __restrict__ counts, int* __restrict__ offsets,
                           int* __restrict__ blocksums)
{
    __shared__ int s[256];
    int i = blockIdx.x * 256 + threadIdx.x;
    int v = (i < N_NODES) ? counts[i] : 0;
    s[threadIdx.x] = v;
    __syncthreads();
    // Hillis-Steele inclusive
    for (int off = 1; off < 256; off <<= 1) {
        int t = (threadIdx.x >= off) ? s[threadIdx.x - off] : 0;
        __syncthreads();
        s[threadIdx.x] += t;
        __syncthreads();
    }
    if (i < N_NODES) offsets[i] = s[threadIdx.x] - v;   // exclusive
    if (threadIdx.x == 255) blocksums[blockIdx.x] = s[255];
}

__global__ void scan_part2(int* __restrict__ blocksums)
{
    __shared__ int s[256];
    int i = threadIdx.x;
    int v = (i < NB_SCAN) ? blocksums[i] : 0;
    s[i] = v;
    __syncthreads();
    for (int off = 1; off < 256; off <<= 1) {
        int t = (i >= off) ? s[i - off] : 0;
        __syncthreads();
        s[i] += t;
        __syncthreads();
    }
    if (i < NB_SCAN) blocksums[i] = s[i] - v;           // exclusive
}

__global__ void scan_part3(int* __restrict__ offsets, const int* __restrict__ blocksums)
{
    int i = blockIdx.x * 256 + threadIdx.x;
    if (i < N_NODES) offsets[i] += blocksums[blockIdx.x];
    if (i == 0) offsets[N_NODES] = N_EDGES;
}

__global__ void fill_kernel(const int* __restrict__ edge_index,
                            const float* __restrict__ w,
                            const int* __restrict__ offsets,
                            int* __restrict__ cursor,
                            int2* __restrict__ edges)
{
    int e = blockIdx.x * blockDim.x + threadIdx.x;
    if (e >= N_EDGES) return;
    int s = edge_index[e];
    int d = edge_index[N_EDGES + e];
    int p = offsets[d] + atomicAdd(&cursor[d], 1);
    edges[p] = make_int2(s, __float_as_int(w[e]));
}

// ---------------- aggregate: out[n] = act( b + sum_{e in CSR[n]} w_e * h[src_e] ) ----
// one warp per node; each lane owns 2 float4 (32B) of the 1KB row
template <bool RELU>
__global__ __launch_bounds__(256)
void aggregate_kernel(const float* __restrict__ h,
                      const int* __restrict__ offsets,
                      const int2* __restrict__ edges,
                      const float* __restrict__ bias,
                      float* __restrict__ out)
{
    int warp = (blockIdx.x * blockDim.x + threadIdx.x) >> 5;
    int lane = threadIdx.x & 31;
    if (warp >= N_NODES) return;

    int beg = offsets[warp];
    int end = offsets[warp + 1];

    const float4* b4 = (const float4*)bias;
    float4 acc0 = b4[lane];
    float4 acc1 = b4[lane + 32];

    const float4* h4 = (const float4*)h;

#pragma unroll 4
    for (int e = beg; e < end; e++) {
        int2  ed = edges[e];
        float we = __int_as_float(ed.y);
        const float4* hr = h4 + (size_t)ed.x * (FDIM / 4);
        float4 v0 = hr[lane];
        float4 v1 = hr[lane + 32];
        acc0.x = fmaf(we, v0.x, acc0.x); acc0.y = fmaf(we, v0.y, acc0.y);
        acc0.z = fmaf(we, v0.z, acc0.z); acc0.w = fmaf(we, v0.w, acc0.w);
        acc1.x = fmaf(we, v1.x, acc1.x); acc1.y = fmaf(we, v1.y, acc1.y);
        acc1.z = fmaf(we, v1.z, acc1.z); acc1.w = fmaf(we, v1.w, acc1.w);
    }

    if (RELU) {
        acc0.x = fmaxf(acc0.x, 0.f); acc0.y = fmaxf(acc0.y, 0.f);
        acc0.z = fmaxf(acc0.z, 0.f); acc0.w = fmaxf(acc0.w, 0.f);
        acc1.x = fmaxf(acc1.x, 0.f); acc1.y = fmaxf(acc1.y, 0.f);
        acc1.z = fmaxf(acc1.z, 0.f); acc1.w = fmaxf(acc1.w, 0.f);
    }

    float4* o4 = (float4*)(out + (size_t)warp * FDIM);
    o4[lane]      = acc0;
    o4[lane + 32] = acc1;
}

// ---------------- GEMM: C[M,256] = A[M,256] @ B[256,256] (reg-prefetch dbuf) ------
__global__ __launch_bounds__(256, 2)
void sgemm_k256(const float* __restrict__ A, const float* __restrict__ B,
                float* __restrict__ C, int M)
{
    const int BM = 128, BN = 128, BK = 8;
    __shared__ float As[BK][BM + 4];
    __shared__ float Bs[BK][BN];

    int tid  = threadIdx.x;
    int row0 = blockIdx.x * BM;
    int col0 = blockIdx.y * BN;

    int tx = tid & 15;
    int ty = tid >> 4;

    int arow = tid >> 1;
    int acol = (tid & 1) * 4;
    int brow = tid >> 5;
    int bcol = (tid & 31) * 4;

    bool aval = (row0 + arow) < M;
    const float* Aptr = A + (size_t)(row0 + arow) * KDIM + acol;
    const float* Bptr = B + (size_t)brow * KDIM + col0 + bcol;

    float acc[8][8];
#pragma unroll
    for (int i = 0; i < 8; i++)
#pragma unroll
        for (int j = 0; j < 8; j++) acc[i][j] = 0.f;

    // prefetch tile 0
    float4 av = aval ? *(const float4*)(Aptr) : make_float4(0.f, 0.f, 0.f, 0.f);
    float4 bv = *(const float4*)(Bptr);

    for (int k0 = 0; k0 < KDIM; k0 += BK) {
        As[acol + 0][arow] = av.x;
        As[acol + 1][arow] = av.y;
        As[acol + 2][arow] = av.z;
        As[acol + 3][arow] = av.w;
        *(float4*)&Bs[brow][bcol] = bv;
        __syncthreads();

        if (k0 + BK < KDIM) {
            av = aval ? *(const float4*)(Aptr + k0 + BK) : make_float4(0.f, 0.f, 0.f, 0.f);
            bv = *(const float4*)(Bptr + (size_t)(k0 + BK) * KDIM);
        }

#pragma unroll
        for (int k = 0; k < BK; k++) {
            float ra[8], rb[8];
#pragma unroll
            for (int i = 0; i < 8; i++) ra[i] = As[k][ty * 8 + i];
#pragma unroll
            for (int j = 0; j < 8; j++) rb[j] = Bs[k][tx * 8 + j];
#pragma unroll
            for (int i = 0; i < 8; i++)
#pragma unroll
                for (int j = 0; j < 8; j++) acc[i][j] = fmaf(ra[i], rb[j], acc[i][j]);
        }
        __syncthreads();
    }

#pragma unroll
    for (int i = 0; i < 8; i++) {
        int r = row0 + ty * 8 + i;
        if (r < M) {
            float4* cp = (float4*)(C + (size_t)r * KDIM + col0 + tx * 8);
            cp[0] = make_float4(acc[i][0], acc[i][1], acc[i][2], acc[i][3]);
            cp[1] = make_float4(acc[i][4], acc[i][5], acc[i][6], acc[i][7]);
        }
    }
}

// ---------------- query head: concat-GEMV + log_softmax (one warp / query) --------
__global__ __launch_bounds__(256)
void final_kernel(const float* __restrict__ h,
                  const int* __restrict__ q,
                  const float* __restrict__ Wl,
                  const float* __restrict__ bl,
                  float* __restrict__ out)
{
    __shared__ float sW[512 * 2];
    __shared__ float sb[2];
    for (int i = threadIdx.x; i < 1024; i += blockDim.x) sW[i] = Wl[i];
    if (threadIdx.x < 2) sb[threadIdx.x] = bl[threadIdx.x];
    __syncthreads();

    int warp = (blockIdx.x * blockDim.x + threadIdx.x) >> 5;
    int lane = threadIdx.x & 31;
    if (warp >= N_QUERY) return;

    int qa = q[2 * warp];
    int qb = q[2 * warp + 1];

    const float4* ha = (const float4*)(h + (size_t)qa * FDIM);
    const float4* hb = (const float4*)(h + (size_t)qb * FDIM);

    float acc0 = 0.f, acc1 = 0.f;
#pragma unroll
    for (int c = 0; c < 2; c++) {
        int f4 = lane + 32 * c;
        int f  = f4 * 4;
        float4 v = ha[f4];
        acc0 += v.x * sW[(f + 0) * 2 + 0] + v.y * sW[(f + 1) * 2 + 0]
              + v.z * sW[(f + 2) * 2 + 0] + v.w * sW[(f + 3) * 2 + 0];
        acc1 += v.x * sW[(f + 0) * 2 + 1] + v.y * sW[(f + 1) * 2 + 1]
              + v.z * sW[(f + 2) * 2 + 1] + v.w * sW[(f + 3) * 2 + 1];
        float4 u = hb[f4];
        int g = 256 + f;
        acc0 += u.x * sW[(g + 0) * 2 + 0] + u.y * sW[(g + 1) * 2 + 0]
              + u.z * sW[(g + 2) * 2 + 0] + u.w * sW[(g + 3) * 2 + 0];
        acc1 += u.x * sW[(g + 0) * 2 + 1] + u.y * sW[(g + 1) * 2 + 1]
              + u.z * sW[(g + 2) * 2 + 1] + u.w * sW[(g + 3) * 2 + 1];
    }
#pragma unroll
    for (int off = 16; off > 0; off >>= 1) {
        acc0 += __shfl_down_sync(0xFFFFFFFFu, acc0, off);
        acc1 += __shfl_down_sync(0xFFFFFFFFu, acc1, off);
    }
    if (lane == 0) {
        float l0 = acc0 + sb[0];
        float l1 = acc1 + sb[1];
        float m  = fmaxf(l0, l1);
        float lse = m + logf(expf(l0 - m) + expf(l1 - m));
        out[2 * warp]     = l0 - lse;
        out[2 * warp + 1] = l1 - lse;
    }
}

// ---------------- launch ----------------
extern "C" void kernel_launch(void* const* d_in, const int* in_sizes, int n_in,
                              void* d_out, int out_size)
{
    const float* x    = (const float*)d_in[0];
    const int*   ei   = (const int*)  d_in[1];
    const int*   qe   = (const int*)  d_in[2];
    const float* ew   = (const float*)d_in[3];
    const float* W1   = (const float*)d_in[4];
    const float* b1   = (const float*)d_in[5];
    const float* W2   = (const float*)d_in[6];
    const float* b2   = (const float*)d_in[7];
    const float* Wl   = (const float*)d_in[8];
    const float* bl   = (const float*)d_in[9];
    float*       out  = (float*)d_out;

    float *h, *a;
    int *counts, *cursor, *offsets, *blocksums;
    int2 *edges;
    cudaGetSymbolAddress((void**)&h,        g_h);
    cudaGetSymbolAddress((void**)&a,        g_a);
    cudaGetSymbolAddress((void**)&counts,   g_counts);
    cudaGetSymbolAddress((void**)&cursor,   g_cursor);
    cudaGetSymbolAddress((void**)&offsets,  g_offsets);
    cudaGetSymbolAddress((void**)&blocksums,g_blocksums);
    cudaGetSymbolAddress((void**)&edges,    g_edges);

    // ---- CSR build (by dst) ----
    zero_kernel<<<(N_NODES + 255) / 256, 256>>>(counts, cursor);
    count_kernel<<<(N_EDGES + 255) / 256, 256>>>(ei, counts);
    scan_part1<<<NB_SCAN, 256>>>(counts, offsets, blocksums);
    scan_part2<<<1, 256>>>(blocksums);
    scan_part3<<<NB_SCAN, 256>>>(offsets, blocksums);
    fill_kernel<<<(N_EDGES + 255) / 256, 256>>>(ei, ew, offsets, cursor, edges);

    dim3 gemm_grid((N_NODES + 127) / 128, 2);
    const int agg_grid = (N_NODES * 32 + 255) / 256;

    // conv1: h = x@W1 ; a = relu(agg(h) + b1)
    sgemm_k256<<<gemm_grid, 256>>>(x, W1, h, N_NODES);
    aggregate_kernel<true><<<agg_grid, 256>>>(h, offsets, edges, b1, a);

    // conv2: h = a@W2 ; a2 (reuse a? no — h dead after) -> write into h? careful:
    // h = a@W2 (read a, write h); then a = agg(h) + b2 (read h, write a). Safe.
    sgemm_k256<<<gemm_grid, 256>>>(a, W2, h, N_NODES);
    aggregate_kernel<false><<<agg_grid, 256>>>(h, offsets, edges, b2, a);

    // link-prediction head
    final_kernel<<<(N_QUERY * 32 + 255) / 256, 256>>>(a, qe, Wl, bl, out);
}